// round 14
// baseline (speedup 1.0000x reference)
#include <cuda_runtime.h>
#include <cuda_bf16.h>
#include <mma.h>
#include <math.h>
#include <cstdint>

using namespace nvcuda;

// Problem constants
#define BB   2
#define SS   2048
#define HH   2048
#define NH   16
#define DD   128
#define MM   (BB*SS)       // 4096 rows
#define KK3  (3*HH)        // augmented K = 6144
#define GN   2048

// Scratch (device globals — no allocation allowed)
__device__ float g_cos[SS*64];
__device__ float g_sin[SS*64];
// augmented bf16 operands for GEMMs
__device__ __nv_bfloat16 g_Asp[(size_t)MM*KK3];       // [Ah | Al | Ah]
__device__ __nv_bfloat16 g_Bsp[(size_t)3*HH*KK3];     // stacked [Wq;Wk;Wv] each [hi|hi|lo]
// pre-split attention operands (bf16 hi/lo)
__device__ __nv_bfloat16 g_qh[(size_t)MM*HH], g_ql[(size_t)MM*HH];
__device__ __nv_bfloat16 g_kh[(size_t)MM*HH], g_kl[(size_t)MM*HH];
__device__ __nv_bfloat16 g_vh[(size_t)MM*HH], g_vl[(size_t)MM*HH];

// ---------------------------------------------------------------------------
// helpers
// ---------------------------------------------------------------------------
__device__ __forceinline__ void bsplit(float v, __nv_bfloat16& h, __nv_bfloat16& l) {
    h = __float2bfloat16(v);
    l = __float2bfloat16(v - __bfloat162float(h));
}
__device__ __forceinline__ uint32_t bpack(__nv_bfloat16 a, __nv_bfloat16 b) {
    return (uint32_t)__bfloat16_as_ushort(a) | ((uint32_t)__bfloat16_as_ushort(b) << 16);
}
__device__ __forceinline__ void split4(float4 v, uint2& hi, uint2& lo) {
    __nv_bfloat16 hx, lx, hy, ly, hz, lz, hw, lw;
    bsplit(v.x, hx, lx); bsplit(v.y, hy, ly);
    bsplit(v.z, hz, lz); bsplit(v.w, hw, lw);
    hi.x = bpack(hx, hy); hi.y = bpack(hz, hw);
    lo.x = bpack(lx, ly); lo.y = bpack(lz, lw);
}
__device__ __forceinline__ uint32_t smem_u32(const void* p) {
    uint32_t a;
    asm("{ .reg .u64 t; cvta.to.shared.u64 t, %1; cvt.u32.u64 %0, t; }" : "=r"(a) : "l"(p));
    return a;
}
#define CP_ASYNC16(dst, src) \
    asm volatile("cp.async.cg.shared.global [%0], [%1], 16;" :: "r"(dst), "l"(src) : "memory")
#define CP_COMMIT() asm volatile("cp.async.commit_group;" ::: "memory")
#define CP_WAIT1()  asm volatile("cp.async.wait_group 1;" ::: "memory")

// ---------------------------------------------------------------------------
// Split kernels (inputs only — one-shot, bandwidth-bound)
// ---------------------------------------------------------------------------
// A-style: src [rows, HH] f32 -> dst [rows, 3*HH] bf16 as [hi | lo | hi]
__global__ void split3_A(const float* __restrict__ src, __nv_bfloat16* __restrict__ dst) {
    int t = blockIdx.x * blockDim.x + threadIdx.x;     // over rows*HH/4
    int r  = t >> 9;           // HH/4 = 512
    int c4 = t & 511;
    float4 v = *(const float4*)&src[(size_t)r * HH + c4 * 4];
    uint2 hi, lo;
    split4(v, hi, lo);
    size_t base = (size_t)r * KK3 + c4 * 4;
    *(uint2*)&dst[base]          = hi;
    *(uint2*)&dst[base + HH]     = lo;
    *(uint2*)&dst[base + 2*HH]   = hi;
}
// B-style: [hi | hi | lo]
__global__ void split3_B(const float* __restrict__ src, __nv_bfloat16* __restrict__ dst) {
    int t = blockIdx.x * blockDim.x + threadIdx.x;
    int r  = t >> 9;
    int c4 = t & 511;
    float4 v = *(const float4*)&src[(size_t)r * HH + c4 * 4];
    uint2 hi, lo;
    split4(v, hi, lo);
    size_t base = (size_t)r * KK3 + c4 * 4;
    *(uint2*)&dst[base]          = hi;
    *(uint2*)&dst[base + HH]     = hi;
    *(uint2*)&dst[base + 2*HH]   = lo;
}

// ---------------------------------------------------------------------------
// RoPE tables (double-precision libm, rounded through reference fp32 path)
// ---------------------------------------------------------------------------
__global__ void rope_tables_kernel() {
    int t = blockIdx.x * blockDim.x + threadIdx.x;
    if (t >= SS * 64) return;
    int i = t & 63;
    int s = t >> 6;
    double invf_d = pow(10000.0, -((double)(2 * i) / 128.0));
    float invf = (float)invf_d;
    float ang = (float)s * invf;
    double a = (double)ang;
    g_cos[t] = (float)cos(a);
    g_sin[t] = (float)sin(a);
}

// ---------------------------------------------------------------------------
// bf16 NT GEMM over augmented K'=6144, mainloop UNCHANGED from R10 (proven).
// CTA 128x128, 4 warps, warp tile 64x64. cp.async 3-stage ring. 2 CTAs/SM.
// Epilogue modes:
//   fuse==0 : plain f32 store to C (output projection)
//   fuse==1 : fused QKV epilogue — smem-stage the f32 tile, then
//             bufi 0 -> RoPE + bf16-split -> g_qh/g_ql
//             bufi 1 -> RoPE + bf16-split -> g_kh/g_kl
//             bufi 2 -> bf16-split        -> g_vh/g_vl
// ---------------------------------------------------------------------------
#define BKG   64
#define ALDS  72                       // smem leading dim (bf16)
#define TILEB (128 * ALDS * 2)         // 18432 B
#define STGB  (2 * TILEB)              // 36864 B
#define NSTG  3
#define GEMM_SMEM (NSTG * STGB)        // 110592 B
#define ELD   132                      // f32 staging leading dim (128x132x4 = 67584 B)

__global__ __launch_bounds__(128, 2) void gemm_nt_bf16(
    const __nv_bfloat16* __restrict__ A, const __nv_bfloat16* __restrict__ B,
    float* __restrict__ C, int fuse)
{
    extern __shared__ __align__(16) char smem[];
    const uint32_t sbase = smem_u32(smem);

    const int tid = threadIdx.x;
    const int w   = tid >> 5;
    const int wm  = w & 1;    // rows wm*64
    const int wn  = w >> 1;   // cols wn*64
    const int bm  = blockIdx.y * 128;
    const int nb  = blockIdx.x;
    const int bufi = nb >> 4;
    const int bn  = (nb & 15) * 128;
    const int brow = bufi * 2048 + bn;   // global B row base

    const int crow = tid >> 3;     // 0..15 (+16 per step)
    const int cc8  = tid & 7;
    const __nv_bfloat16* agp = A + (size_t)(bm + crow) * KK3 + cc8 * 8;
    const __nv_bfloat16* bgp = B + (size_t)(brow + crow) * KK3 + cc8 * 8;
    const uint32_t soff = (uint32_t)(crow * (ALDS * 2) + cc8 * 16);

    auto load_stage = [&](int stg, int k0) {
        uint32_t sA = sbase + stg * STGB + soff;
        uint32_t sB = sA + TILEB;
        const __nv_bfloat16* ag = agp + k0;
        const __nv_bfloat16* bg = bgp + k0;
        #pragma unroll
        for (int i = 0; i < 8; i++) {
            CP_ASYNC16(sA, ag);
            CP_ASYNC16(sB, bg);
            sA += 16 * (ALDS * 2);
            sB += 16 * (ALDS * 2);
            ag += (size_t)16 * KK3;
            bg += (size_t)16 * KK3;
        }
        CP_COMMIT();
    };

    wmma::fragment<wmma::accumulator, 16, 16, 16, float> acc[4][4];
    #pragma unroll
    for (int i = 0; i < 4; i++)
        #pragma unroll
        for (int j = 0; j < 4; j++)
            wmma::fill_fragment(acc[i][j], 0.0f);

    load_stage(0, 0);
    load_stage(1, BKG);

    const int nkt = KK3 / BKG;   // 96
    for (int kt = 0; kt < nkt; kt++) {
        CP_WAIT1();
        __syncthreads();

        if (kt + 2 < nkt) load_stage((kt + 2) % NSTG, (kt + 2) * BKG);

        const char* stg = smem + (kt % NSTG) * STGB;
        const __nv_bfloat16* sA = (const __nv_bfloat16*)stg;
        const __nv_bfloat16* sB = (const __nv_bfloat16*)(stg + TILEB);

        #pragma unroll
        for (int kk = 0; kk < 4; kk++) {
            wmma::fragment<wmma::matrix_a, 16, 16, 16, __nv_bfloat16, wmma::row_major> af[4];
            #pragma unroll
            for (int i = 0; i < 4; i++)
                wmma::load_matrix_sync(af[i], sA + (wm * 64 + i * 16) * ALDS + kk * 16, ALDS);
            #pragma unroll
            for (int j = 0; j < 4; j++) {
                wmma::fragment<wmma::matrix_b, 16, 16, 16, __nv_bfloat16, wmma::col_major> bf;
                wmma::load_matrix_sync(bf, sB + (wn * 64 + j * 16) * ALDS + kk * 16, ALDS);
                #pragma unroll
                for (int i = 0; i < 4; i++)
                    wmma::mma_sync(acc[i][j], af[i], bf, acc[i][j]);
            }
        }
    }

    if (fuse == 0) {
        #pragma unroll
        for (int i = 0; i < 4; i++)
            #pragma unroll
            for (int j = 0; j < 4; j++)
                wmma::store_matrix_sync(
                    C + (size_t)(bm + wm * 64 + i * 16) * GN + bn + wn * 64 + j * 16,
                    acc[i][j], GN, wmma::mem_row_major);
        return;
    }

    // ---- fused QKV epilogue ----
    __syncthreads();   // all warps done reading cp.async stages before overwrite
    float* stage = (float*)smem;
    #pragma unroll
    for (int i = 0; i < 4; i++)
        #pragma unroll
        for (int j = 0; j < 4; j++)
            wmma::store_matrix_sync(stage + (wm * 64 + i * 16) * ELD + wn * 64 + j * 16,
                                    acc[i][j], ELD, wmma::mem_row_major);
    __syncthreads();

    __nv_bfloat16 *dh, *dl;
    if (bufi == 0)      { dh = g_qh; dl = g_ql; }
    else if (bufi == 1) { dh = g_kh; dl = g_kl; }
    else                { dh = g_vh; dl = g_vl; }
    const bool do_rope = (bufi < 2);

    // 128 rows x 64 pairs; l -> (row = l>>6, d = l&63); consecutive tid = consecutive d
    for (int l = tid; l < 128 * 64; l += 128) {
        int lrow = l >> 6;
        int d    = l & 63;
        int grow = bm + lrow;
        float x1 = stage[lrow * ELD + d];
        float x2 = stage[lrow * ELD + d + 64];
        float y1, y2;
        if (do_rope) {
            int s = grow & (SS - 1);
            float c  = g_cos[(s << 6) + d];
            float sn = g_sin[(s << 6) + d];
            y1 = x1 * c - x2 * sn;
            y2 = x2 * c + x1 * sn;
        } else {
            y1 = x1; y2 = x2;
        }
        size_t base = (size_t)grow * HH + bn;
        __nv_bfloat16 hh, ll;
        bsplit(y1, hh, ll); dh[base + d]      = hh; dl[base + d]      = ll;
        bsplit(y2, hh, ll); dh[base + d + 64] = hh; dl[base + d + 64] = ll;
    }
}

// ---------------------------------------------------------------------------
// Flash attention (causal), bf16x3 scores + bf16x3 P*V. (R13 core, unchanged)
// Output written directly into g_Asp augmented layout [hi | lo | hi].
// ---------------------------------------------------------------------------
#define ALD    136   // bf16 leading dim for Q/K/V tiles
#define PS_LD  72
#define PLD    72
#define OLD    136

#define OFF_QH  0
#define OFF_QL  (OFF_QH + 64 * ALD * 2)
#define OFF_KH  (OFF_QL + 64 * ALD * 2)
#define OFF_KL  (OFF_KH + 64 * ALD * 2)
#define OFF_VH  (OFF_KL + 64 * ALD * 2)
#define OFF_VL  (OFF_VH + 64 * ALD * 2)
#define OFF_PS  (OFF_VL + 64 * ALD * 2)
#define OFF_PH  (OFF_PS + 64 * PS_LD * 4)
#define OFF_PL  (OFF_PH + 64 * PLD * 2)
#define OFF_OS  (OFF_PL + 64 * PLD * 2)
#define ATT_SMEM (OFF_OS + 64 * OLD * 4)

__global__ __launch_bounds__(256) void attn_kernel() {
    const int qt = (int)gridDim.x - 1 - (int)blockIdx.x;  // heavy tiles first
    const int h  = blockIdx.y;
    const int b  = blockIdx.z;

    extern __shared__ __align__(16) char smc[];
    __nv_bfloat16* Qh = (__nv_bfloat16*)(smc + OFF_QH);
    __nv_bfloat16* Ql = (__nv_bfloat16*)(smc + OFF_QL);
    __nv_bfloat16* Kh = (__nv_bfloat16*)(smc + OFF_KH);
    __nv_bfloat16* Kl = (__nv_bfloat16*)(smc + OFF_KL);
    __nv_bfloat16* Vh = (__nv_bfloat16*)(smc + OFF_VH);
    __nv_bfloat16* Vl = (__nv_bfloat16*)(smc + OFF_VL);
    float*         Ps = (float*)        (smc + OFF_PS);
    __nv_bfloat16* Ph = (__nv_bfloat16*)(smc + OFF_PH);
    __nv_bfloat16* Pl = (__nv_bfloat16*)(smc + OFF_PL);
    float*         Os = (float*)        (smc + OFF_OS);

    const int tid = threadIdx.x;
    const int w   = tid >> 5;
    const int wm  = w >> 1;   // 0..3 (16 q-rows each)
    const int wn  = w & 1;    // 0..1

    const size_t hb = (size_t)b * SS * HH + (size_t)h * DD;
    const __nv_bfloat16* qhp = g_qh + hb;
    const __nv_bfloat16* qlp = g_ql + hb;
    const __nv_bfloat16* khp = g_kh + hb;
    const __nv_bfloat16* klp = g_kl + hb;
    const __nv_bfloat16* vhp = g_vh + hb;
    const __nv_bfloat16* vlp = g_vl + hb;

    // Load Q tile (hi+lo): 64 rows x 16 16B-chunks each
    for (int l = tid; l < 64 * 16; l += 256) {
        int rr = l >> 4, c8 = l & 15;
        size_t g = (size_t)(qt * 64 + rr) * HH + c8 * 8;
        *(uint4*)&Qh[rr * ALD + c8 * 8] = *(const uint4*)&qhp[g];
        *(uint4*)&Ql[rr * ALD + c8 * 8] = *(const uint4*)&qlp[g];
    }

    const int r     = tid >> 2;   // softmax/O row (4 threads per row)
    const int sub   = tid & 3;
    const int qglob = qt * 64 + r;
    const float SCALE = sqrtf(128.0f);

    float row_m = -INFINITY;
    float row_l = 0.0f;
    float o[32];
    #pragma unroll
    for (int i = 0; i < 32; i++) o[i] = 0.0f;

    for (int kt = 0; kt <= qt; ++kt) {
        const int kbase = kt * 64;

        // K/V tile load (overwrite safe: all warps passed post-Os barrier)
        for (int l = tid; l < 64 * 16; l += 256) {
            int rr = l >> 4, c8 = l & 15;
            size_t g = (size_t)(kbase + rr) * HH + c8 * 8;
            *(uint4*)&Kh[rr * ALD + c8 * 8] = *(const uint4*)&khp[g];
            *(uint4*)&Kl[rr * ALD + c8 * 8] = *(const uint4*)&klp[g];
            *(uint4*)&Vh[rr * ALD + c8 * 8] = *(const uint4*)&vhp[g];
            *(uint4*)&Vl[rr * ALD + c8 * 8] = *(const uint4*)&vlp[g];
        }
        __syncthreads();

        // ---- scores = Q * K^T (bf16x3), warp tile 16x32 ----
        {
            wmma::fragment<wmma::accumulator, 16, 16, 16, float> sacc[2];
            wmma::fill_fragment(sacc[0], 0.0f);
            wmma::fill_fragment(sacc[1], 0.0f);
            #pragma unroll
            for (int ks = 0; ks < 8; ks++) {
                wmma::fragment<wmma::matrix_a, 16, 16, 16, __nv_bfloat16, wmma::row_major> a_hi, a_lo;
                wmma::load_matrix_sync(a_hi, Qh + (wm * 16) * ALD + ks * 16, ALD);
                wmma::load_matrix_sync(a_lo, Ql + (wm * 16) * ALD + ks * 16, ALD);
                #pragma unroll
                for (int j = 0; j < 2; j++) {
                    wmma::fragment<wmma::matrix_b, 16, 16, 16, __nv_bfloat16, wmma::col_major> b_hi, b_lo;
                    wmma::load_matrix_sync(b_hi, Kh + (wn * 32 + j * 16) * ALD + ks * 16, ALD);
                    wmma::load_matrix_sync(b_lo, Kl + (wn * 32 + j * 16) * ALD + ks * 16, ALD);
                    wmma::mma_sync(sacc[j], a_hi, b_hi, sacc[j]);
                    wmma::mma_sync(sacc[j], a_lo, b_hi, sacc[j]);
                    wmma::mma_sync(sacc[j], a_hi, b_lo, sacc[j]);
                }
            }
            #pragma unroll
            for (int j = 0; j < 2; j++)
                wmma::store_matrix_sync(Ps + (wm * 16) * PS_LD + wn * 32 + j * 16,
                                        sacc[j], PS_LD, wmma::mem_row_major);
        }
        __syncthreads();

        // ---- online softmax; write P as bf16 hi/lo ----
        float alpha;
        {
            float vals[16];
            float tmax = -INFINITY;
            #pragma unroll
            for (int c0 = 0; c0 < 16; c0++) {
                int c = sub * 16 + c0;
                float sc = Ps[r * PS_LD + c] * SCALE;
                if (kbase + c > qglob) sc = -INFINITY;
                vals[c0] = sc;
                tmax = fmaxf(tmax, sc);
            }
            tmax = fmaxf(tmax, __shfl_xor_sync(0xffffffffu, tmax, 1));
            tmax = fmaxf(tmax, __shfl_xor_sync(0xffffffffu, tmax, 2));
            float newm = fmaxf(row_m, tmax);
            float lsum = 0.0f;
            #pragma unroll
            for (int c0 = 0; c0 < 16; c0++) {
                float p = __expf(vals[c0] - newm);
                __nv_bfloat16 hp, lp;
                bsplit(p, hp, lp);
                Ph[r * PLD + sub * 16 + c0] = hp;
                Pl[r * PLD + sub * 16 + c0] = lp;
                lsum += p;
            }
            lsum += __shfl_xor_sync(0xffffffffu, lsum, 1);
            lsum += __shfl_xor_sync(0xffffffffu, lsum, 2);
            alpha = __expf(row_m - newm);
            row_l = row_l * alpha + lsum;
            row_m = newm;
        }
        __syncthreads();

        // ---- O_tile = P * V (bf16x3), warp tile 16x64 ----
        {
            wmma::fragment<wmma::accumulator, 16, 16, 16, float> oac[4];
            #pragma unroll
            for (int j = 0; j < 4; j++) wmma::fill_fragment(oac[j], 0.0f);
            #pragma unroll
            for (int ks = 0; ks < 4; ks++) {
                wmma::fragment<wmma::matrix_a, 16, 16, 16, __nv_bfloat16, wmma::row_major> p_hi, p_lo;
                wmma::load_matrix_sync(p_hi, Ph + (wm * 16) * PLD + ks * 16, PLD);
                wmma::load_matrix_sync(p_lo, Pl + (wm * 16) * PLD + ks * 16, PLD);
                #pragma unroll
                for (int j = 0; j < 4; j++) {
                    wmma::fragment<wmma::matrix_b, 16, 16, 16, __nv_bfloat16, wmma::row_major> v_hi, v_lo;
                    wmma::load_matrix_sync(v_hi, Vh + (ks * 16) * ALD + wn * 64 + j * 16, ALD);
                    wmma::load_matrix_sync(v_lo, Vl + (ks * 16) * ALD + wn * 64 + j * 16, ALD);
                    wmma::mma_sync(oac[j], p_hi, v_hi, oac[j]);
                    wmma::mma_sync(oac[j], p_lo, v_hi, oac[j]);
                    wmma::mma_sync(oac[j], p_hi, v_lo, oac[j]);
                }
            }
            #pragma unroll
            for (int j = 0; j < 4; j++)
                wmma::store_matrix_sync(Os + (wm * 16) * OLD + wn * 64 + j * 16,
                                        oac[j], OLD, wmma::mem_row_major);
        }
        __syncthreads();

        // ---- O register update (protected by next iteration's first barrier) ----
        #pragma unroll
        for (int i = 0; i < 32; i++)
            o[i] = o[i] * alpha + Os[r * OLD + sub + 4 * i];
    }

    // ---- write ctx directly into augmented Asp layout [hi | lo | hi] ----
    float inv = 1.0f / row_l;
    const int grow = b * SS + qglob;
    const size_t base = (size_t)grow * KK3 + (size_t)h * DD;
    #pragma unroll
    for (int i = 0; i < 32; i++) {
        float y = o[i] * inv;
        __nv_bfloat16 hh, ll;
        bsplit(y, hh, ll);
        int c = sub + 4 * i;
        g_Asp[base + c]          = hh;
        g_Asp[base + HH + c]     = ll;
        g_Asp[base + 2 * HH + c] = hh;
    }
}

// ---------------------------------------------------------------------------
// Launch
// ---------------------------------------------------------------------------
extern "C" void kernel_launch(void* const* d_in, const int* in_sizes, int n_in,
                              void* d_out, int out_size) {
    const float* x  = (const float*)d_in[0];
    const float* Wq = (const float*)d_in[1];
    const float* Wk = (const float*)d_in[2];
    const float* Wv = (const float*)d_in[3];
    const float* Wo = (const float*)d_in[4];
    float* out = (float*)d_out;

    __nv_bfloat16 *Asp, *Bsp;
    cudaGetSymbolAddress((void**)&Asp, g_Asp);
    cudaGetSymbolAddress((void**)&Bsp, g_Bsp);

    cudaFuncSetAttribute(gemm_nt_bf16,
                         cudaFuncAttributeMaxDynamicSharedMemorySize, GEMM_SMEM);
    cudaFuncSetAttribute(attn_kernel,
                         cudaFuncAttributeMaxDynamicSharedMemorySize, ATT_SMEM);

    rope_tables_kernel<<<(SS * 64 + 255) / 256, 256>>>();

    // input splits: x -> Asp; Wq/Wk/Wv -> stacked Bsp rows
    split3_A<<<(MM * HH / 4) / 256, 256>>>(x, Asp);
    split3_B<<<(HH * HH / 4) / 256, 256>>>(Wq, Bsp);
    split3_B<<<(HH * HH / 4) / 256, 256>>>(Wk, Bsp + (size_t)2048 * KK3);
    split3_B<<<(HH * HH / 4) / 256, 256>>>(Wv, Bsp + (size_t)4096 * KK3);

    // fused QKV GEMM with rope/split epilogue -> g_qh/.../g_vl
    gemm_nt_bf16<<<dim3(48, MM / 128), 128, GEMM_SMEM>>>(Asp, Bsp, nullptr, 1);

    // attention writes augmented Asp directly
    attn_kernel<<<dim3(SS / 64, NH, BB), 256, ATT_SMEM>>>();

    // output projection (plain f32 epilogue)
    split3_B<<<(HH * HH / 4) / 256, 256>>>(Wo, Bsp);
    gemm_nt_bf16<<<dim3(16, MM / 128), 128, GEMM_SMEM>>>(Asp, Bsp, out, 0);
}

// round 16
// speedup vs baseline: 1.1326x; 1.1326x over previous
#include <cuda_runtime.h>
#include <cuda_bf16.h>
#include <mma.h>
#include <math.h>
#include <cstdint>

using namespace nvcuda;

// Problem constants
#define BB   2
#define SS   2048
#define HH   2048
#define NH   16
#define DD   128
#define MM   (BB*SS)       // 4096 rows
#define KK3  (3*HH)        // augmented K = 6144
#define GN   2048

// Scratch (device globals — no allocation allowed)
__device__ float g_q[(size_t)MM*HH];
__device__ float g_k[(size_t)MM*HH];
__device__ float g_v[(size_t)MM*HH];
__device__ float g_ctx[(size_t)MM*HH];
__device__ float g_cos[SS*64];
__device__ float g_sin[SS*64];
// augmented bf16 operands for GEMMs
__device__ __nv_bfloat16 g_Asp[(size_t)MM*KK3];       // [Ah | Al | Ah]
__device__ __nv_bfloat16 g_Bsp[(size_t)3*HH*KK3];     // stacked [Wq;Wk;Wv] each [hi|hi|lo]
// pre-split attention operands (bf16 hi/lo)
__device__ __nv_bfloat16 g_qh[(size_t)MM*HH], g_ql[(size_t)MM*HH];
__device__ __nv_bfloat16 g_kh[(size_t)MM*HH], g_kl[(size_t)MM*HH];
__device__ __nv_bfloat16 g_vh[(size_t)MM*HH], g_vl[(size_t)MM*HH];

// ---------------------------------------------------------------------------
// helpers
// ---------------------------------------------------------------------------
__device__ __forceinline__ void bsplit(float v, __nv_bfloat16& h, __nv_bfloat16& l) {
    h = __float2bfloat16(v);
    l = __float2bfloat16(v - __bfloat162float(h));
}
__device__ __forceinline__ uint32_t bpack(__nv_bfloat16 a, __nv_bfloat16 b) {
    return (uint32_t)__bfloat16_as_ushort(a) | ((uint32_t)__bfloat16_as_ushort(b) << 16);
}
__device__ __forceinline__ void split4(float4 v, uint2& hi, uint2& lo) {
    __nv_bfloat16 hx, lx, hy, ly, hz, lz, hw, lw;
    bsplit(v.x, hx, lx); bsplit(v.y, hy, ly);
    bsplit(v.z, hz, lz); bsplit(v.w, hw, lw);
    hi.x = bpack(hx, hy); hi.y = bpack(hz, hw);
    lo.x = bpack(lx, ly); lo.y = bpack(lz, lw);
}
__device__ __forceinline__ uint32_t smem_u32(const void* p) {
    uint32_t a;
    asm("{ .reg .u64 t; cvta.to.shared.u64 t, %1; cvt.u32.u64 %0, t; }" : "=r"(a) : "l"(p));
    return a;
}
#define CP_ASYNC16(dst, src) \
    asm volatile("cp.async.cg.shared.global [%0], [%1], 16;" :: "r"(dst), "l"(src) : "memory")
#define CP_COMMIT() asm volatile("cp.async.commit_group;" ::: "memory")
#define CP_WAIT1()  asm volatile("cp.async.wait_group 1;" ::: "memory")

// ---------------------------------------------------------------------------
// Split kernels (inputs only — one-shot, bandwidth-bound)
// ---------------------------------------------------------------------------
// A-style: src [rows, HH] f32 -> dst [rows, 3*HH] bf16 as [hi | lo | hi]
__global__ void split3_A(const float* __restrict__ src, __nv_bfloat16* __restrict__ dst) {
    int t = blockIdx.x * blockDim.x + threadIdx.x;     // over rows*HH/4
    int r  = t >> 9;           // HH/4 = 512
    int c4 = t & 511;
    float4 v = *(const float4*)&src[(size_t)r * HH + c4 * 4];
    uint2 hi, lo;
    split4(v, hi, lo);
    size_t base = (size_t)r * KK3 + c4 * 4;
    *(uint2*)&dst[base]          = hi;
    *(uint2*)&dst[base + HH]     = lo;
    *(uint2*)&dst[base + 2*HH]   = hi;
}
// B-style: [hi | hi | lo]
__global__ void split3_B(const float* __restrict__ src, __nv_bfloat16* __restrict__ dst) {
    int t = blockIdx.x * blockDim.x + threadIdx.x;
    int r  = t >> 9;
    int c4 = t & 511;
    float4 v = *(const float4*)&src[(size_t)r * HH + c4 * 4];
    uint2 hi, lo;
    split4(v, hi, lo);
    size_t base = (size_t)r * KK3 + c4 * 4;
    *(uint2*)&dst[base]          = hi;
    *(uint2*)&dst[base + HH]     = hi;
    *(uint2*)&dst[base + 2*HH]   = lo;
}
// all three weights in one launch (rows stacked: Wq rows 0..2047, Wk, Wv)
__global__ void split3_B3(const float* __restrict__ W0, const float* __restrict__ W1,
                          const float* __restrict__ W2, __nv_bfloat16* __restrict__ dst) {
    int t = blockIdx.x * blockDim.x + threadIdx.x;     // over 3*HH*HH/4
    int r  = t >> 9;           // global row 0..6143
    int c4 = t & 511;
    int wsel = r >> 11;        // 0,1,2
    int lr   = r & 2047;
    const float* src = (wsel == 0) ? W0 : ((wsel == 1) ? W1 : W2);
    float4 v = *(const float4*)&src[(size_t)lr * HH + c4 * 4];
    uint2 hi, lo;
    split4(v, hi, lo);
    size_t base = (size_t)r * KK3 + c4 * 4;
    *(uint2*)&dst[base]          = hi;
    *(uint2*)&dst[base + HH]     = hi;
    *(uint2*)&dst[base + 2*HH]   = lo;
}
// plain hi/lo split (for v)
__global__ void split2(const float* __restrict__ src,
                       __nv_bfloat16* __restrict__ dh, __nv_bfloat16* __restrict__ dl) {
    int t = blockIdx.x * blockDim.x + threadIdx.x;     // over MM*HH/4
    float4 v = *(const float4*)&src[(size_t)t * 4];
    uint2 hi, lo;
    split4(v, hi, lo);
    *(uint2*)&dh[(size_t)t * 4] = hi;
    *(uint2*)&dl[(size_t)t * 4] = lo;
}

// ---------------------------------------------------------------------------
// RoPE tables (double-precision libm, rounded through reference fp32 path)
// ---------------------------------------------------------------------------
__global__ void rope_tables_kernel() {
    int t = blockIdx.x * blockDim.x + threadIdx.x;
    if (t >= SS * 64) return;
    int i = t & 63;
    int s = t >> 6;
    double invf_d = pow(10000.0, -((double)(2 * i) / 128.0));
    float invf = (float)invf_d;
    float ang = (float)s * invf;
    double a = (double)ang;
    g_cos[t] = (float)cos(a);
    g_sin[t] = (float)sin(a);
}

// RoPE + hi/lo split fused: reads f32 GEMM output, writes bf16 hi/lo buffers.
__global__ void rope_split_kernel(const float* __restrict__ src,
                                  __nv_bfloat16* __restrict__ dh,
                                  __nv_bfloat16* __restrict__ dl) {
    int t = blockIdx.x * blockDim.x + threadIdx.x;
    const int total = MM * NH * 64;
    if (t >= total) return;
    int d   = t & 63;
    int h   = (t >> 6) & (NH - 1);
    int row = t >> 10;
    int s   = row & (SS - 1);
    float c  = g_cos[(s << 6) + d];
    float sn = g_sin[(s << 6) + d];
    size_t idx = (size_t)row * HH + (h << 7) + d;
    float x1 = src[idx];
    float x2 = src[idx + 64];
    float y1 = x1 * c - x2 * sn;
    float y2 = x2 * c + x1 * sn;
    __nv_bfloat16 hh, ll;
    bsplit(y1, hh, ll); dh[idx]      = hh; dl[idx]      = ll;
    bsplit(y2, hh, ll); dh[idx + 64] = hh; dl[idx + 64] = ll;
}

// ---------------------------------------------------------------------------
// bf16 NT GEMM over augmented K'=6144, C f32.  (UNCHANGED from R10 — proven)
// CTA 128x128, 4 warps, warp tile 64x64. cp.async 3-stage ring. 2 CTAs/SM.
// N-block routing: nb>>4 selects output buffer (fused QKV); B rows stacked.
// ---------------------------------------------------------------------------
#define BKG   64
#define ALDS  72                       // smem leading dim (bf16)
#define TILEB (128 * ALDS * 2)         // 18432 B
#define STGB  (2 * TILEB)              // 36864 B
#define NSTG  3
#define GEMM_SMEM (NSTG * STGB)        // 110592 B

__global__ __launch_bounds__(128, 2) void gemm_nt_bf16(
    const __nv_bfloat16* __restrict__ A, const __nv_bfloat16* __restrict__ B,
    float* __restrict__ C0, float* __restrict__ C1, float* __restrict__ C2)
{
    extern __shared__ __align__(16) char smem[];
    const uint32_t sbase = smem_u32(smem);

    const int tid = threadIdx.x;
    const int w   = tid >> 5;
    const int wm  = w & 1;    // rows wm*64
    const int wn  = w >> 1;   // cols wn*64
    const int bm  = blockIdx.y * 128;
    const int nb  = blockIdx.x;
    const int bufi = nb >> 4;
    const int bn  = (nb & 15) * 128;
    float* C = (bufi == 0) ? C0 : ((bufi == 1) ? C1 : C2);
    const int brow = bufi * 2048 + bn;   // global B row base

    const int crow = tid >> 3;     // 0..15 (+16 per step)
    const int cc8  = tid & 7;
    const __nv_bfloat16* agp = A + (size_t)(bm + crow) * KK3 + cc8 * 8;
    const __nv_bfloat16* bgp = B + (size_t)(brow + crow) * KK3 + cc8 * 8;
    const uint32_t soff = (uint32_t)(crow * (ALDS * 2) + cc8 * 16);

    auto load_stage = [&](int stg, int k0) {
        uint32_t sA = sbase + stg * STGB + soff;
        uint32_t sB = sA + TILEB;
        const __nv_bfloat16* ag = agp + k0;
        const __nv_bfloat16* bg = bgp + k0;
        #pragma unroll
        for (int i = 0; i < 8; i++) {
            CP_ASYNC16(sA, ag);
            CP_ASYNC16(sB, bg);
            sA += 16 * (ALDS * 2);
            sB += 16 * (ALDS * 2);
            ag += (size_t)16 * KK3;
            bg += (size_t)16 * KK3;
        }
        CP_COMMIT();
    };

    wmma::fragment<wmma::accumulator, 16, 16, 16, float> acc[4][4];
    #pragma unroll
    for (int i = 0; i < 4; i++)
        #pragma unroll
        for (int j = 0; j < 4; j++)
            wmma::fill_fragment(acc[i][j], 0.0f);

    load_stage(0, 0);
    load_stage(1, BKG);

    const int nkt = KK3 / BKG;   // 96
    for (int kt = 0; kt < nkt; kt++) {
        CP_WAIT1();
        __syncthreads();

        if (kt + 2 < nkt) load_stage((kt + 2) % NSTG, (kt + 2) * BKG);

        const char* stg = smem + (kt % NSTG) * STGB;
        const __nv_bfloat16* sA = (const __nv_bfloat16*)stg;
        const __nv_bfloat16* sB = (const __nv_bfloat16*)(stg + TILEB);

        #pragma unroll
        for (int kk = 0; kk < 4; kk++) {
            wmma::fragment<wmma::matrix_a, 16, 16, 16, __nv_bfloat16, wmma::row_major> af[4];
            #pragma unroll
            for (int i = 0; i < 4; i++)
                wmma::load_matrix_sync(af[i], sA + (wm * 64 + i * 16) * ALDS + kk * 16, ALDS);
            #pragma unroll
            for (int j = 0; j < 4; j++) {
                wmma::fragment<wmma::matrix_b, 16, 16, 16, __nv_bfloat16, wmma::col_major> bf;
                wmma::load_matrix_sync(bf, sB + (wn * 64 + j * 16) * ALDS + kk * 16, ALDS);
                #pragma unroll
                for (int i = 0; i < 4; i++)
                    wmma::mma_sync(acc[i][j], af[i], bf, acc[i][j]);
            }
        }
    }

    #pragma unroll
    for (int i = 0; i < 4; i++)
        #pragma unroll
        for (int j = 0; j < 4; j++)
            wmma::store_matrix_sync(
                C + (size_t)(bm + wm * 64 + i * 16) * GN + bn + wn * 64 + j * 16,
                acc[i][j], GN, wmma::mem_row_major);
}

// ---------------------------------------------------------------------------
// Flash attention (causal), bf16x3 scores + bf16x3 P*V.  (R13 core)
// NEW: K/V tiles arrive via cp.async with two rotating commit groups —
//   K(kt+1) issued after the post-scores barrier (K dead there),
//   V(kt+1) issued after the post-PV barrier (V dead there).
// Loop top waits group A (K), pre-PV waits group B (V). Barrier count: 4.
// ---------------------------------------------------------------------------
#define ALD    136   // bf16 leading dim for Q/K/V tiles
#define PS_LD  72
#define PLD    72
#define OLD    136

#define OFF_QH  0
#define OFF_QL  (OFF_QH + 64 * ALD * 2)
#define OFF_KH  (OFF_QL + 64 * ALD * 2)
#define OFF_KL  (OFF_KH + 64 * ALD * 2)
#define OFF_VH  (OFF_KL + 64 * ALD * 2)
#define OFF_VL  (OFF_VH + 64 * ALD * 2)
#define OFF_PS  (OFF_VL + 64 * ALD * 2)
#define OFF_PH  (OFF_PS + 64 * PS_LD * 4)
#define OFF_PL  (OFF_PH + 64 * PLD * 2)
#define OFF_OS  (OFF_PL + 64 * PLD * 2)
#define ATT_SMEM (OFF_OS + 64 * OLD * 4)

__global__ __launch_bounds__(256) void attn_kernel() {
    const int qt = (int)gridDim.x - 1 - (int)blockIdx.x;  // heavy tiles first
    const int h  = blockIdx.y;
    const int b  = blockIdx.z;

    extern __shared__ __align__(16) char smc[];
    __nv_bfloat16* Qh = (__nv_bfloat16*)(smc + OFF_QH);
    __nv_bfloat16* Ql = (__nv_bfloat16*)(smc + OFF_QL);
    __nv_bfloat16* Kh = (__nv_bfloat16*)(smc + OFF_KH);
    __nv_bfloat16* Kl = (__nv_bfloat16*)(smc + OFF_KL);
    __nv_bfloat16* Vh = (__nv_bfloat16*)(smc + OFF_VH);
    __nv_bfloat16* Vl = (__nv_bfloat16*)(smc + OFF_VL);
    float*         Ps = (float*)        (smc + OFF_PS);
    __nv_bfloat16* Ph = (__nv_bfloat16*)(smc + OFF_PH);
    __nv_bfloat16* Pl = (__nv_bfloat16*)(smc + OFF_PL);
    float*         Os = (float*)        (smc + OFF_OS);

    const int tid = threadIdx.x;
    const int w   = tid >> 5;
    const int wm  = w >> 1;   // 0..3 (16 q-rows each)
    const int wn  = w & 1;    // 0..1

    const size_t hb = (size_t)b * SS * HH + (size_t)h * DD;
    const __nv_bfloat16* qhp = g_qh + hb;
    const __nv_bfloat16* qlp = g_ql + hb;
    const __nv_bfloat16* khp = g_kh + hb;
    const __nv_bfloat16* klp = g_kl + hb;
    const __nv_bfloat16* vhp = g_vh + hb;
    const __nv_bfloat16* vlp = g_vl + hb;

    const uint32_t uKh = smem_u32(Kh);
    const uint32_t uKl = smem_u32(Kl);
    const uint32_t uVh = smem_u32(Vh);
    const uint32_t uVl = smem_u32(Vl);

    // per-thread tile-copy coords: 64 rows x 16 chunks(16B), 256 thr -> 4 each
    const int trr = tid >> 2;        // base row pattern (rr = l>>4)
    // (we keep the l-loop form for clarity; 4 iterations each)

    // ---- prologue: Q via regular stores; K(0), V(0) via cp.async ----
    for (int l = tid; l < 64 * 16; l += 256) {
        int rr = l >> 4, c8 = l & 15;
        size_t g = (size_t)(qt * 64 + rr) * HH + c8 * 8;
        *(uint4*)&Qh[rr * ALD + c8 * 8] = *(const uint4*)&qhp[g];
        *(uint4*)&Ql[rr * ALD + c8 * 8] = *(const uint4*)&qlp[g];
    }
    for (int l = tid; l < 64 * 16; l += 256) {               // group A: K(0)
        int rr = l >> 4, c8 = l & 15;
        size_t g = (size_t)rr * HH + c8 * 8;
        uint32_t so = (uint32_t)(rr * ALD + c8 * 8) * 2;
        CP_ASYNC16(uKh + so, khp + g);
        CP_ASYNC16(uKl + so, klp + g);
    }
    CP_COMMIT();
    for (int l = tid; l < 64 * 16; l += 256) {               // group B: V(0)
        int rr = l >> 4, c8 = l & 15;
        size_t g = (size_t)rr * HH + c8 * 8;
        uint32_t so = (uint32_t)(rr * ALD + c8 * 8) * 2;
        CP_ASYNC16(uVh + so, vhp + g);
        CP_ASYNC16(uVl + so, vlp + g);
    }
    CP_COMMIT();

    const int r     = tid >> 2;   // softmax/O row (4 threads per row)
    const int sub   = tid & 3;
    const int qglob = qt * 64 + r;
    const float SCALE = sqrtf(128.0f);

    float row_m = -INFINITY;
    float row_l = 0.0f;
    float o[32];
    #pragma unroll
    for (int i = 0; i < 32; i++) o[i] = 0.0f;

    for (int kt = 0; kt <= qt; ++kt) {
        const int kbase = kt * 64;

        CP_WAIT1();          // K(kt) landed (most-recent group = V may pend)
        __syncthreads();     // K visible to all; Q visible on first iter; Os reads done

        // ---- scores = Q * K^T (bf16x3), warp tile 16x32 ----
        {
            wmma::fragment<wmma::accumulator, 16, 16, 16, float> sacc[2];
            wmma::fill_fragment(sacc[0], 0.0f);
            wmma::fill_fragment(sacc[1], 0.0f);
            #pragma unroll
            for (int ks = 0; ks < 8; ks++) {
                wmma::fragment<wmma::matrix_a, 16, 16, 16, __nv_bfloat16, wmma::row_major> a_hi, a_lo;
                wmma::load_matrix_sync(a_hi, Qh + (wm * 16) * ALD + ks * 16, ALD);
                wmma::load_matrix_sync(a_lo, Ql + (wm * 16) * ALD + ks * 16, ALD);
                #pragma unroll
                for (int j = 0; j < 2; j++) {
                    wmma::fragment<wmma::matrix_b, 16, 16, 16, __nv_bfloat16, wmma::col_major> b_hi, b_lo;
                    wmma::load_matrix_sync(b_hi, Kh + (wn * 32 + j * 16) * ALD + ks * 16, ALD);
                    wmma::load_matrix_sync(b_lo, Kl + (wn * 32 + j * 16) * ALD + ks * 16, ALD);
                    wmma::mma_sync(sacc[j], a_hi, b_hi, sacc[j]);
                    wmma::mma_sync(sacc[j], a_lo, b_hi, sacc[j]);
                    wmma::mma_sync(sacc[j], a_hi, b_lo, sacc[j]);
                }
            }
            #pragma unroll
            for (int j = 0; j < 2; j++)
                wmma::store_matrix_sync(Ps + (wm * 16) * PS_LD + wn * 32 + j * 16,
                                        sacc[j], PS_LD, wmma::mem_row_major);
        }
        __syncthreads();     // scores done; Ps visible; K now dead

        // ---- prefetch K(kt+1) into the K buffer (group A) ----
        if (kt < qt) {
            const int nb2 = kbase + 64;
            for (int l = tid; l < 64 * 16; l += 256) {
                int rr = l >> 4, c8 = l & 15;
                size_t g = (size_t)(nb2 + rr) * HH + c8 * 8;
                uint32_t so = (uint32_t)(rr * ALD + c8 * 8) * 2;
                CP_ASYNC16(uKh + so, khp + g);
                CP_ASYNC16(uKl + so, klp + g);
            }
        }
        CP_COMMIT();         // group committed even if empty (uniform counts)

        // ---- online softmax; write P as bf16 hi/lo ----
        float alpha;
        {
            float vals[16];
            float tmax = -INFINITY;
            #pragma unroll
            for (int c0 = 0; c0 < 16; c0++) {
                int c = sub * 16 + c0;
                float sc = Ps[r * PS_LD + c] * SCALE;
                if (kbase + c > qglob) sc = -INFINITY;
                vals[c0] = sc;
                tmax = fmaxf(tmax, sc);
            }
            tmax = fmaxf(tmax, __shfl_xor_sync(0xffffffffu, tmax, 1));
            tmax = fmaxf(tmax, __shfl_xor_sync(0xffffffffu, tmax, 2));
            float newm = fmaxf(row_m, tmax);
            float lsum = 0.0f;
            #pragma unroll
            for (int c0 = 0; c0 < 16; c0++) {
                float p = __expf(vals[c0] - newm);
                __nv_bfloat16 hp, lp;
                bsplit(p, hp, lp);
                Ph[r * PLD + sub * 16 + c0] = hp;
                Pl[r * PLD + sub * 16 + c0] = lp;
                lsum += p;
            }
            lsum += __shfl_xor_sync(0xffffffffu, lsum, 1);
            lsum += __shfl_xor_sync(0xffffffffu, lsum, 2);
            alpha = __expf(row_m - newm);
            row_l = row_l * alpha + lsum;
            row_m = newm;
        }

        CP_WAIT1();          // V(kt) landed (most-recent group = K(kt+1) may pend)
        __syncthreads();     // Ph/Pl + V visible

        // ---- O_tile = P * V (bf16x3), warp tile 16x64 ----
        {
            wmma::fragment<wmma::accumulator, 16, 16, 16, float> oac[4];
            #pragma unroll
            for (int j = 0; j < 4; j++) wmma::fill_fragment(oac[j], 0.0f);
            #pragma unroll
            for (int ks = 0; ks < 4; ks++) {
                wmma::fragment<wmma::matrix_a, 16, 16, 16, __nv_bfloat16, wmma::row_major> p_hi, p_lo;
                wmma::load_matrix_sync(p_hi, Ph + (wm * 16) * PLD + ks * 16, PLD);
                wmma::load_matrix_sync(p_lo, Pl + (wm * 16) * PLD + ks * 16, PLD);
                #pragma unroll
                for (int j = 0; j < 4; j++) {
                    wmma::fragment<wmma::matrix_b, 16, 16, 16, __nv_bfloat16, wmma::row_major> v_hi, v_lo;
                    wmma::load_matrix_sync(v_hi, Vh + (ks * 16) * ALD + wn * 64 + j * 16, ALD);
                    wmma::load_matrix_sync(v_lo, Vl + (ks * 16) * ALD + wn * 64 + j * 16, ALD);
                    wmma::mma_sync(oac[j], p_hi, v_hi, oac[j]);
                    wmma::mma_sync(oac[j], p_lo, v_hi, oac[j]);
                    wmma::mma_sync(oac[j], p_hi, v_lo, oac[j]);
                }
            }
            #pragma unroll
            for (int j = 0; j < 4; j++)
                wmma::store_matrix_sync(Os + (wm * 16) * OLD + wn * 64 + j * 16,
                                        oac[j], OLD, wmma::mem_row_major);
        }
        __syncthreads();     // PV done; Os visible; V now dead

        // ---- prefetch V(kt+1) into the V buffer (group B) ----
        if (kt < qt) {
            const int nb2 = kbase + 64;
            for (int l = tid; l < 64 * 16; l += 256) {
                int rr = l >> 4, c8 = l & 15;
                size_t g = (size_t)(nb2 + rr) * HH + c8 * 8;
                uint32_t so = (uint32_t)(rr * ALD + c8 * 8) * 2;
                CP_ASYNC16(uVh + so, vhp + g);
                CP_ASYNC16(uVl + so, vlp + g);
            }
        }
        CP_COMMIT();

        // ---- O register update (Os reads complete before next top barrier) ----
        #pragma unroll
        for (int i = 0; i < 32; i++)
            o[i] = o[i] * alpha + Os[r * OLD + sub + 4 * i];
    }

    float inv = 1.0f / row_l;
    float* cp = g_ctx + (size_t)(b * SS + qglob) * HH + (size_t)h * DD;
    #pragma unroll
    for (int i = 0; i < 32; i++)
        cp[sub + 4 * i] = o[i] * inv;
}

// ---------------------------------------------------------------------------
// Launch  (QKV GEMM is the 4th launch -> gets the ncu capture slot)
// ---------------------------------------------------------------------------
extern "C" void kernel_launch(void* const* d_in, const int* in_sizes, int n_in,
                              void* d_out, int out_size) {
    const float* x  = (const float*)d_in[0];
    const float* Wq = (const float*)d_in[1];
    const float* Wk = (const float*)d_in[2];
    const float* Wv = (const float*)d_in[3];
    const float* Wo = (const float*)d_in[4];
    float* out = (float*)d_out;

    float *q, *k, *v, *ctx;
    cudaGetSymbolAddress((void**)&q,   g_q);
    cudaGetSymbolAddress((void**)&k,   g_k);
    cudaGetSymbolAddress((void**)&v,   g_v);
    cudaGetSymbolAddress((void**)&ctx, g_ctx);
    __nv_bfloat16 *Asp, *Bsp, *qh, *ql, *kh, *kl, *vh, *vl;
    cudaGetSymbolAddress((void**)&Asp, g_Asp);
    cudaGetSymbolAddress((void**)&Bsp, g_Bsp);
    cudaGetSymbolAddress((void**)&qh, g_qh);
    cudaGetSymbolAddress((void**)&ql, g_ql);
    cudaGetSymbolAddress((void**)&kh, g_kh);
    cudaGetSymbolAddress((void**)&kl, g_kl);
    cudaGetSymbolAddress((void**)&vh, g_vh);
    cudaGetSymbolAddress((void**)&vl, g_vl);

    cudaFuncSetAttribute(gemm_nt_bf16,
                         cudaFuncAttributeMaxDynamicSharedMemorySize, GEMM_SMEM);
    cudaFuncSetAttribute(attn_kernel,
                         cudaFuncAttributeMaxDynamicSharedMemorySize, ATT_SMEM);

    // 1: rope tables   2: x split   3: all-W split   4: QKV GEMM (profiled)
    rope_tables_kernel<<<(SS * 64 + 255) / 256, 256>>>();
    split3_A<<<(MM * HH / 4) / 256, 256>>>(x, Asp);
    split3_B3<<<(3 * HH * HH / 4) / 256, 256>>>(Wq, Wk, Wv, Bsp);
    gemm_nt_bf16<<<dim3(48, MM / 128), 128, GEMM_SMEM>>>(Asp, Bsp, q, k, v);

    // RoPE + split q/k; split v
    int rt = MM * NH * 64;
    rope_split_kernel<<<rt / 256, 256>>>(q, qh, ql);
    rope_split_kernel<<<rt / 256, 256>>>(k, kh, kl);
    split2<<<(MM * HH / 4) / 256, 256>>>(v, vh, vl);

    attn_kernel<<<dim3(SS / 64, NH, BB), 256, ATT_SMEM>>>();

    // output projection
    split3_A<<<(MM * HH / 4) / 256, 256>>>(ctx, Asp);
    split3_B<<<(HH * HH / 4) / 256, 256>>>(Wo, Bsp);
    gemm_nt_bf16<<<dim3(16, MM / 128), 128, GEMM_SMEM>>>(Asp, Bsp, out, out, out);
}